// round 14
// baseline (speedup 1.0000x reference)
#include <cuda_runtime.h>
#include <cuda_fp16.h>
#include <cstdint>

#define HH 256
#define WW 256
#define BATCH 16
#define HW 65536
#define CIN 12
#define CNOISE 3
#define PERCC 48
#define HID 128
#define TDIM 256
#define TPB 512
#define TP 256
#define NTILES (BATCH * HW / TP)   // 4096 (tile = one image row)

// SMEM word (b32) offsets
#define OW2   0       // W2 [128 rows][64 words] swizzled, K-permuted fp16-pairs
#define OW1   8192    // W1 [128 rows][32 words] (24 real) swizzled
#define OW3   12288   // W3 [16 rows][64 words] swizzled, K-permuted (rows 12-15 zero)
#define OWPK  13312   // conv weights packed: [12 grp][9 q][4 floats]
#define OBPK  13744   // conv bias packed: [12 grp][4 floats]
#define OB1   13792   // b1 128 fp32
#define OB2   13920   // b2 128 fp32
#define OH1   14048   // h1 [256 px][64 words] (quad-private rows)
#define OH2   30432   // h2 [256 px][64 words] (quad-private rows) -- separate!
#define OPH2  46816   // perc single buffer [256 px][32 words]
#define SMEM_WORDS 55008
#define SMEM_BYTES (SMEM_WORDS * 4)   // 220032 <= 232448

typedef unsigned long long ull;

#define FMA2(d, a, b) \
    asm("fma.rn.f32x2 %0, %1, %2, %0;" : "+l"(d) : "l"(a), "l"(b))
#define PACKF(out, lo, hi) \
    asm("mov.b64 %0, {%1, %2};" : "=l"(out) : "f"(lo), "f"(hi))
#define UNPACKF(lo, hi, in) \
    asm("mov.b64 {%0, %1}, %2;" : "=f"(lo), "=f"(hi) : "l"(in))

// Quad-scoped named barrier: 4 warps / 128 threads, ids 1..4
#define BARQ(id) \
    asm volatile("bar.sync %0, 128;" :: "r"(id) : "memory")

static __device__ __forceinline__ uint32_t packh2(float lo, float hi) {
    __half2 h = __floats2half2_rn(lo, hi);
    return *(uint32_t*)&h;
}

static __device__ __forceinline__ uint32_t smem_u32(const void* p) {
    uint32_t a;
    asm("{ .reg .u64 t; cvta.to.shared.u64 t, %1; cvt.u32.u64 %0, t; }"
        : "=r"(a) : "l"(p));
    return a;
}

static __device__ __forceinline__ void mma16(float d[4], const uint32_t a[4],
                                             uint32_t b0, uint32_t b1) {
    asm volatile(
        "mma.sync.aligned.m16n8k16.row.col.f32.f16.f16.f32 "
        "{%0,%1,%2,%3}, {%4,%5,%6,%7}, {%8,%9}, {%0,%1,%2,%3};"
        : "+f"(d[0]), "+f"(d[1]), "+f"(d[2]), "+f"(d[3])
        : "r"(a[0]), "r"(a[1]), "r"(a[2]), "r"(a[3]), "r"(b0), "r"(b1));
}

#define LDSM4(r, a) \
    asm volatile("ldmatrix.sync.aligned.m8n8.x4.shared.b16 {%0,%1,%2,%3}, [%4];" \
        : "=r"((r)[0]), "=r"((r)[1]), "=r"((r)[2]), "=r"((r)[3]) : "r"(a))

__device__ float g_emb[BATCH * CNOISE];

// ---------------------------------------------------------------------------
__global__ void emb_kernel(const int* __restrict__ t,
                           const float* __restrict__ w_time,
                           const float* __restrict__ b_time) {
    __shared__ float ss[TDIM];
    int b = blockIdx.x, k = threadIdx.x;
    float tb = (float)t[b];
    int f = (k < TDIM / 2) ? k : (k - TDIM / 2);
    const double LN1E4 = 9.210340371976184;
    float invf = (float)exp(-LN1E4 * ((double)(2 * f) / 256.0));
    float ang = tb * invf;
    float pe = (float)((k < TDIM / 2) ? sin((double)ang) : cos((double)ang));
    ss[k] = pe / (1.0f + (float)exp(-(double)pe));
    __syncthreads();
    if (k < CNOISE) {
        float acc = b_time[k];
        for (int q = 0; q < TDIM; q++)
            acc = fmaf(ss[q], w_time[k * TDIM + q], acc);
        g_emb[b * CNOISE + k] = acc;
    }
}

// ---------------------------------------------------------------------------
// Conv split: load windows (gmem only — hoistable above L3 MMAs), then
// compute + store to perc (phase-safe: perc's last reader is this tile's L1).
// ---------------------------------------------------------------------------
static __device__ __forceinline__ void conv_load(
    const float* __restrict__ xin, const float* __restrict__ hin,
    float win[6][9], int b, int y, int cpx, int chalf) {
#pragma unroll
    for (int gi = 0; gi < 6; gi++) {
        int g = chalf * 6 + gi;
        const float* src = (g < CNOISE)
            ? (xin + ((size_t)b * CNOISE + g) * HW)
            : (hin + ((size_t)b * (CIN - CNOISE) + (g - CNOISE)) * HW);
#pragma unroll
        for (int dy = -1; dy <= 1; dy++)
#pragma unroll
            for (int dx = -1; dx <= 1; dx++) {
                int yy = y + dy, xx = cpx + dx;
                float v = 0.0f;
                if (yy >= 0 && yy < HH && xx >= 0 && xx < WW)
                    v = __ldg(src + yy * WW + xx);
                win[gi][(dy + 1) * 3 + (dx + 1)] = v;
            }
    }
}

static __device__ __forceinline__ void conv_compute(
    const float win[6][9], const float* sm, uint32_t* smU,
    int cpx, int chalf) {
    int swz = (cpx & 7) << 2;
#pragma unroll
    for (int gi = 0; gi < 6; gi++) {
        int g = chalf * 6 + gi;
        ulonglong2 bb = *(const ulonglong2*)(sm + OBPK + g * 4);
        ull a01 = bb.x, a23 = bb.y;
#pragma unroll
        for (int q = 0; q < 9; q++) {
            ull wd;
            PACKF(wd, win[gi][q], win[gi][q]);
            ulonglong2 ww = *(const ulonglong2*)(sm + OWPK + (g * 9 + q) * 4);
            FMA2(a01, wd, ww.x);
            FMA2(a23, wd, ww.y);
        }
        float a0, a1, a2, a3;
        UNPACKF(a0, a1, a01);
        UNPACKF(a2, a3, a23);
        *(uint2*)(smU + OPH2 + cpx * 32 + ((2 * g) ^ swz)) =
            make_uint2(packh2(a0, a1), packh2(a2, a3));
    }
}

// ---------------------------------------------------------------------------
// Persistent pipeline, fp16 m16n8k16, 16 warps in 4 independent quads.
// 3 barriers/tile (h1/h2 separate regions); conv LDGs hoisted over L3 MMAs.
// ---------------------------------------------------------------------------
__global__ void __launch_bounds__(TPB, 1)
canet_main(const float* __restrict__ xin, const float* __restrict__ hin,
           const float* __restrict__ wp, const float* __restrict__ bp,
           const float* __restrict__ w1, const float* __restrict__ b1,
           const float* __restrict__ w2, const float* __restrict__ b2,
           const float* __restrict__ w3, float* __restrict__ dout) {
    extern __shared__ float sm[];
    uint32_t* smU = (uint32_t*)sm;
    const int tx = threadIdx.x;

    // ---- one-time staging ----
    for (int i = tx; i < 1024; i += TPB) smU[OW3 + i] = 0u;
    __syncthreads();
    for (int i = tx; i < HID * 64; i += TPB) {       // W2, K-permuted
        int o = i >> 6, kw = i & 63;
        int kc = 16 * (kw >> 3) + (kw & 7);
        smU[OW2 + o * 64 + (kw ^ ((o & 7) << 2))] =
            packh2(w2[o * HID + kc], w2[o * HID + kc + 8]);
    }
    for (int i = tx; i < HID * 24; i += TPB) {       // W1, natural K
        int o = i / 24, kw = i % 24;
        smU[OW1 + o * 32 + (kw ^ ((o & 7) << 2))] =
            packh2(w1[o * PERCC + 2 * kw], w1[o * PERCC + 2 * kw + 1]);
    }
    for (int i = tx; i < CIN * 64; i += TPB) {       // W3, K-permuted
        int o = i >> 6, kw = i & 63;
        int kc = 16 * (kw >> 3) + (kw & 7);
        smU[OW3 + o * 64 + (kw ^ ((o & 7) << 2))] =
            packh2(w3[o * HID + kc], w3[o * HID + kc + 8]);
    }
    for (int i = tx; i < 108; i += TPB) {            // conv weights packed
        int g = i / 9, q = i % 9;
        float4 v = make_float4(wp[(4 * g + 0) * 9 + q], wp[(4 * g + 1) * 9 + q],
                               wp[(4 * g + 2) * 9 + q], wp[(4 * g + 3) * 9 + q]);
        *(float4*)(sm + OWPK + i * 4) = v;
    }
    if (tx < 12)
        *(float4*)(sm + OBPK + tx * 4) =
            make_float4(bp[4 * tx], bp[4 * tx + 1], bp[4 * tx + 2], bp[4 * tx + 3]);
    if (tx < HID) { sm[OB1 + tx] = b1[tx]; sm[OB2 + tx] = b2[tx]; }
    __syncthreads();

    const uint32_t sbase = smem_u32(sm);
    const int w    = tx >> 5, lane = tx & 31;
    const int grp  = lane >> 2, t4 = lane & 3;
    const int quad = w >> 2;             // 0..3, owns px [64*quad, 64*quad+64)
    const int bid  = quad + 1;           // named barrier id
    const int cb   = (w & 3) * 32;       // channel base (32 ch per warp)
    const int pxb  = quad * 64;          // pixel base
    const int pxb3 = w * 16;             // L3 pixel base (within quad range)

    // ---- ldmatrix per-lane invariant addressing ----
    const int swlo = (lane & 1) << 2;
    const int swhi = (lane & 6) << 2;
    const int cA   = ((lane >> 4) << 2) ^ swlo;
    const int cB   = (((lane >> 3) & 1) << 2) ^ swlo;
    const int lr   = lane & 15;
    const int bRow = (lane & 7) + ((lane >> 4) << 3);

    uint32_t aW1[2], aW2[2], bP0[4], bH1[4];
#pragma unroll
    for (int i = 0; i < 2; i++) {
        aW1[i] = sbase + 4 * (OW1 + (cb + 16 * i + lr) * 32 + cA);
        aW2[i] = sbase + 4 * (OW2 + (cb + 16 * i + lr) * 64 + cA);
    }
#pragma unroll
    for (int j = 0; j < 4; j++) {
        bP0[j] = sbase + 4 * (OPH2 + (pxb + 16 * j + bRow) * 32 + cB);
        bH1[j] = sbase + 4 * (OH1 + (pxb + 16 * j + bRow) * 64 + cB);
    }
    const uint32_t aW3 = sbase + 4 * (OW3 + lr * 64 + cA);
    const uint32_t bH2 = sbase + 4 * (OH2 + (pxb3 + bRow) * 64 + cB);

    float b1v[2][2], b2v[2][2];
#pragma unroll
    for (int i = 0; i < 2; i++) {
        b1v[i][0] = sm[OB1 + cb + 16 * i + grp];
        b1v[i][1] = sm[OB1 + cb + 16 * i + 8 + grp];
        b2v[i][0] = sm[OB2 + cb + 16 * i + grp];
        b2v[i][1] = sm[OB2 + cb + 16 * i + 8 + grp];
    }

    // conv mapping: quad-local. 128 threads cover 64 px x 2 channel-halves.
    const int tq    = tx & 127;
    const int cpx   = pxb + (tq & 63);
    const int chalf = tq >> 6;

    // ---- prologue: conv for first tile (quad's rows) ----
    {
        int t0 = blockIdx.x;
        float win[6][9];
        conv_load(xin, hin, win, t0 >> 8, t0 & 255, cpx, chalf);
        conv_compute(win, sm, smU, cpx, chalf);
    }
    BARQ(bid);

    for (int tile = blockIdx.x; tile < NTILES; tile += gridDim.x) {
        const int b = tile >> 8;
        const int y = tile & 255;

        // ---- L1: 32ch x 64px per warp, K=48; relu-store -> h1 ----
        {
            float acc[2][8][4];
#pragma unroll
            for (int i = 0; i < 2; i++)
#pragma unroll
                for (int j = 0; j < 8; j++) {
                    acc[i][j][0] = b1v[i][0];
                    acc[i][j][1] = b1v[i][0];
                    acc[i][j][2] = b1v[i][1];
                    acc[i][j][3] = b1v[i][1];
                }
#pragma unroll
            for (int s = 0; s < 3; s++) {
                uint32_t ds = (uint32_t)(((8 * s) ^ swhi) << 2);
                uint32_t a0[4], a1[4], bb[4][4];
                LDSM4(a0, aW1[0] + ds);
                LDSM4(a1, aW1[1] + ds);
#pragma unroll
                for (int jj = 0; jj < 4; jj++) LDSM4(bb[jj], bP0[jj] + ds);
#pragma unroll
                for (int jj = 0; jj < 4; jj++) {
                    mma16(acc[0][2 * jj],     a0, bb[jj][0], bb[jj][1]);
                    mma16(acc[1][2 * jj],     a1, bb[jj][0], bb[jj][1]);
                    mma16(acc[0][2 * jj + 1], a0, bb[jj][2], bb[jj][3]);
                    mma16(acc[1][2 * jj + 1], a1, bb[jj][2], bb[jj][3]);
                }
            }
#pragma unroll
            for (int i = 0; i < 2; i++) {
                int wi = (cb >> 1) + 8 * i + grp;
#pragma unroll
                for (int j = 0; j < 8; j++) {
                    float v0 = fmaxf(acc[i][j][0], 0.0f);
                    float v1 = fmaxf(acc[i][j][1], 0.0f);
                    float v2 = fmaxf(acc[i][j][2], 0.0f);
                    float v3 = fmaxf(acc[i][j][3], 0.0f);
                    int px0 = pxb + 8 * j + 2 * t4;
                    smU[OH1 + px0 * 64 + (wi ^ ((px0 & 7) << 2))] = packh2(v0, v2);
                    smU[OH1 + (px0 + 1) * 64 + (wi ^ (((px0 + 1) & 7) << 2))] =
                        packh2(v1, v3);
                }
            }
        }
        BARQ(bid);   // bar A: h1 complete

        // ---- L2: MMA (reads h1) + relu-store -> h2 (separate region) ----
        {
            float acc2[2][8][4];
#pragma unroll
            for (int i = 0; i < 2; i++)
#pragma unroll
                for (int j = 0; j < 8; j++) {
                    acc2[i][j][0] = b2v[i][0];
                    acc2[i][j][1] = b2v[i][0];
                    acc2[i][j][2] = b2v[i][1];
                    acc2[i][j][3] = b2v[i][1];
                }
#pragma unroll
            for (int s = 0; s < 8; s++) {
                uint32_t ds = (uint32_t)(((8 * s) ^ swhi) << 2);
                uint32_t a0[4], a1[4], bb[4][4];
                LDSM4(a0, aW2[0] + ds);
                LDSM4(a1, aW2[1] + ds);
#pragma unroll
                for (int jj = 0; jj < 4; jj++) LDSM4(bb[jj], bH1[jj] + ds);
#pragma unroll
                for (int jj = 0; jj < 4; jj++) {
                    mma16(acc2[0][2 * jj],     a0, bb[jj][0], bb[jj][1]);
                    mma16(acc2[1][2 * jj],     a1, bb[jj][0], bb[jj][1]);
                    mma16(acc2[0][2 * jj + 1], a0, bb[jj][2], bb[jj][3]);
                    mma16(acc2[1][2 * jj + 1], a1, bb[jj][2], bb[jj][3]);
                }
            }
            // store directly (no barrier needed: h2 is a separate region)
#pragma unroll
            for (int i = 0; i < 2; i++) {
                int wi = (cb >> 1) + 8 * i + grp;
#pragma unroll
                for (int j = 0; j < 8; j++) {
                    float v0 = fmaxf(acc2[i][j][0], 0.0f);
                    float v1 = fmaxf(acc2[i][j][1], 0.0f);
                    float v2 = fmaxf(acc2[i][j][2], 0.0f);
                    float v3 = fmaxf(acc2[i][j][3], 0.0f);
                    int px0 = pxb + 8 * j + 2 * t4;
                    smU[OH2 + px0 * 64 + (wi ^ ((px0 & 7) << 2))] = packh2(v0, v2);
                    smU[OH2 + (px0 + 1) * 64 + (wi ^ (((px0 + 1) & 7) << 2))] =
                        packh2(v1, v3);
                }
            }
        }
        BARQ(bid);   // bar B: h2 complete (also: h1 reads complete)

        // ---- L3 phase: conv-LDG hoist, L3 MMA, epilogue, conv compute ----
        {
            int nt = tile + gridDim.x;
            bool havenext = nt < NTILES;
            float win[6][9];
            if (havenext)
                conv_load(xin, hin, win, nt >> 8, nt & 255, cpx, chalf);

            float acc[2][4];
#pragma unroll
            for (int j = 0; j < 2; j++)
#pragma unroll
                for (int q = 0; q < 4; q++) acc[j][q] = 0.0f;
#pragma unroll
            for (int s = 0; s < 8; s++) {
                uint32_t ds = (uint32_t)(((8 * s) ^ swhi) << 2);
                uint32_t a[4], bb[4];
                LDSM4(a, aW3 + ds);
                LDSM4(bb, bH2 + ds);
                mma16(acc[0], a, bb[0], bb[1]);
                mma16(acc[1], a, bb[2], bb[3]);
            }
            float* out_noise = dout + (size_t)BATCH * 9 * HW;
            float embv = (grp < CNOISE) ? __ldg(&g_emb[b * 3 + grp]) : 0.0f;
#pragma unroll
            for (int j = 0; j < 2; j++) {
                int px0 = pxb3 + 8 * j + 2 * t4;
                size_t yx = (size_t)y * WW + px0;
                if (grp < CNOISE) {
                    *(float2*)(out_noise + ((size_t)b * 3 + grp) * HW + yx) =
                        make_float2(acc[j][0] + embv, acc[j][1] + embv);
                } else {
                    *(float2*)(dout + ((size_t)b * 9 + (grp - 3)) * HW + yx) =
                        make_float2(acc[j][0], acc[j][1]);
                }
                if (grp < 4) {
                    *(float2*)(dout + ((size_t)b * 9 + (grp + 5)) * HW + yx) =
                        make_float2(acc[j][2], acc[j][3]);
                }
            }

            if (havenext)
                conv_compute(win, sm, smU, cpx, chalf);
        }
        BARQ(bid);   // bar C: perc (next tile) complete; h2 reads complete
    }
}

extern "C" void kernel_launch(void* const* d_in, const int* in_sizes, int n_in,
                              void* d_out, int out_size) {
    const float* x      = (const float*)d_in[0];
    const float* hid    = (const float*)d_in[1];
    const int*   t      = (const int*)d_in[2];
    const float* wp     = (const float*)d_in[3];
    const float* bp     = (const float*)d_in[4];
    const float* w1     = (const float*)d_in[5];
    const float* b1     = (const float*)d_in[6];
    const float* w2     = (const float*)d_in[7];
    const float* b2     = (const float*)d_in[8];
    const float* w3     = (const float*)d_in[9];
    const float* w_time = (const float*)d_in[10];
    const float* b_time = (const float*)d_in[11];
    float* out = (float*)d_out;

    cudaFuncSetAttribute(canet_main,
                         cudaFuncAttributeMaxDynamicSharedMemorySize,
                         SMEM_BYTES);

    int nsm = 148;
    if (cudaDeviceGetAttribute(&nsm, cudaDevAttrMultiProcessorCount, 0)
        != cudaSuccess || nsm <= 0)
        nsm = 148;

    emb_kernel<<<BATCH, TDIM>>>(t, w_time, b_time);
    canet_main<<<nsm, TPB, SMEM_BYTES>>>(
        x, hid, wp, bp, w1, b1, w2, b2, w3, out);
}

// round 15
// speedup vs baseline: 1.0304x; 1.0304x over previous
#include <cuda_runtime.h>
#include <cuda_fp16.h>
#include <cstdint>

#define HH 256
#define WW 256
#define BATCH 16
#define HW 65536
#define CIN 12
#define CNOISE 3
#define PERCC 48
#define HID 128
#define TDIM 256
#define TPB 512
#define TP 256
#define NTILES (BATCH * HW / TP)   // 4096 (tile = one image row)

// SMEM word (b32) offsets  (R13-winner layout: 154 KB -> L1D carveout ~73KB)
#define OW2   0       // W2 [128 rows][64 words] swizzled, K-permuted fp16-pairs
#define OW1   8192    // W1 [128 rows][32 words] (24 real) swizzled
#define OW3   12288   // W3 [16 rows][64 words] swizzled, K-permuted (rows 12-15 zero)
#define OWPK  13312   // conv weights packed: [12 grp][9 q][4 floats]
#define OBPK  13744   // conv bias packed: [12 grp][4 floats]
#define OB1   13792   // b1 128 fp32
#define OB2   13920   // b2 128 fp32
#define OH1   14048   // h region [256 px][64 words]: h1 then h2 (quad-private rows)
#define OPH2  30432   // perc single buffer [256 px][32 words] (quad-private rows)
#define SMEM_WORDS 38624
#define SMEM_BYTES (SMEM_WORDS * 4)   // 154496

typedef unsigned long long ull;

#define FMA2(d, a, b) \
    asm("fma.rn.f32x2 %0, %1, %2, %0;" : "+l"(d) : "l"(a), "l"(b))
#define PACKF(out, lo, hi) \
    asm("mov.b64 %0, {%1, %2};" : "=l"(out) : "f"(lo), "f"(hi))
#define UNPACKF(lo, hi, in) \
    asm("mov.b64 {%0, %1}, %2;" : "=f"(lo), "=f"(hi) : "l"(in))

// Quad-scoped named barrier: 4 warps / 128 threads, ids 1..4
#define BARQ(id) \
    asm volatile("bar.sync %0, 128;" :: "r"(id) : "memory")

static __device__ __forceinline__ uint32_t packh2(float lo, float hi) {
    __half2 h = __floats2half2_rn(lo, hi);
    return *(uint32_t*)&h;
}

static __device__ __forceinline__ uint32_t smem_u32(const void* p) {
    uint32_t a;
    asm("{ .reg .u64 t; cvta.to.shared.u64 t, %1; cvt.u32.u64 %0, t; }"
        : "=r"(a) : "l"(p));
    return a;
}

static __device__ __forceinline__ void mma16(float d[4], const uint32_t a[4],
                                             uint32_t b0, uint32_t b1) {
    asm volatile(
        "mma.sync.aligned.m16n8k16.row.col.f32.f16.f16.f32 "
        "{%0,%1,%2,%3}, {%4,%5,%6,%7}, {%8,%9}, {%0,%1,%2,%3};"
        : "+f"(d[0]), "+f"(d[1]), "+f"(d[2]), "+f"(d[3])
        : "r"(a[0]), "r"(a[1]), "r"(a[2]), "r"(a[3]), "r"(b0), "r"(b1));
}

#define LDSM4(r, a) \
    asm volatile("ldmatrix.sync.aligned.m8n8.x4.shared.b16 {%0,%1,%2,%3}, [%4];" \
        : "=r"((r)[0]), "=r"((r)[1]), "=r"((r)[2]), "=r"((r)[3]) : "r"(a))

__device__ float g_emb[BATCH * CNOISE];

// ---------------------------------------------------------------------------
__global__ void emb_kernel(const int* __restrict__ t,
                           const float* __restrict__ w_time,
                           const float* __restrict__ b_time) {
    __shared__ float ss[TDIM];
    int b = blockIdx.x, k = threadIdx.x;
    float tb = (float)t[b];
    int f = (k < TDIM / 2) ? k : (k - TDIM / 2);
    const double LN1E4 = 9.210340371976184;
    float invf = (float)exp(-LN1E4 * ((double)(2 * f) / 256.0));
    float ang = tb * invf;
    float pe = (float)((k < TDIM / 2) ? sin((double)ang) : cos((double)ang));
    ss[k] = pe / (1.0f + (float)exp(-(double)pe));
    __syncthreads();
    if (k < CNOISE) {
        float acc = b_time[k];
        for (int q = 0; q < TDIM; q++)
            acc = fmaf(ss[q], w_time[k * TDIM + q], acc);
        g_emb[b * CNOISE + k] = acc;
    }
}

// ---------------------------------------------------------------------------
// Conv split: load (gmem only, hoistable over L3 MMAs) + compute/store.
// Single perc buffer is phase-safe: conv_compute runs in the L3 phase, after
// this tile's L1 consumed perc; BARQ separates it from the next L1.
// ---------------------------------------------------------------------------
static __device__ __forceinline__ void conv_load(
    const float* __restrict__ xin, const float* __restrict__ hin,
    float win[6][9], int b, int y, int cpx, int chalf) {
#pragma unroll
    for (int gi = 0; gi < 6; gi++) {
        int g = chalf * 6 + gi;
        const float* src = (g < CNOISE)
            ? (xin + ((size_t)b * CNOISE + g) * HW)
            : (hin + ((size_t)b * (CIN - CNOISE) + (g - CNOISE)) * HW);
#pragma unroll
        for (int dy = -1; dy <= 1; dy++)
#pragma unroll
            for (int dx = -1; dx <= 1; dx++) {
                int yy = y + dy, xx = cpx + dx;
                float v = 0.0f;
                if (yy >= 0 && yy < HH && xx >= 0 && xx < WW)
                    v = __ldg(src + yy * WW + xx);
                win[gi][(dy + 1) * 3 + (dx + 1)] = v;
            }
    }
}

static __device__ __forceinline__ void conv_compute(
    const float win[6][9], const float* sm, uint32_t* smU,
    int cpx, int chalf) {
    int swz = (cpx & 7) << 2;
#pragma unroll
    for (int gi = 0; gi < 6; gi++) {
        int g = chalf * 6 + gi;
        ulonglong2 bb = *(const ulonglong2*)(sm + OBPK + g * 4);
        ull a01 = bb.x, a23 = bb.y;
#pragma unroll
        for (int q = 0; q < 9; q++) {
            ull wd;
            PACKF(wd, win[gi][q], win[gi][q]);
            ulonglong2 ww = *(const ulonglong2*)(sm + OWPK + (g * 9 + q) * 4);
            FMA2(a01, wd, ww.x);
            FMA2(a23, wd, ww.y);
        }
        float a0, a1, a2, a3;
        UNPACKF(a0, a1, a01);
        UNPACKF(a2, a3, a23);
        *(uint2*)(smU + OPH2 + cpx * 32 + ((2 * g) ^ swz)) =
            make_uint2(packh2(a0, a1), packh2(a2, a3));
    }
}

// ---------------------------------------------------------------------------
// Persistent pipeline, fp16 m16n8k16, 16 warps in 4 independent quads.
// R13-winner structure (4 quad-barriers, shared h region, bias-init accs,
// single perc buffer / big L1D carveout) + conv-LDG hoist over L3 MMAs.
// ---------------------------------------------------------------------------
__global__ void __launch_bounds__(TPB, 1)
canet_main(const float* __restrict__ xin, const float* __restrict__ hin,
           const float* __restrict__ wp, const float* __restrict__ bp,
           const float* __restrict__ w1, const float* __restrict__ b1,
           const float* __restrict__ w2, const float* __restrict__ b2,
           const float* __restrict__ w3, float* __restrict__ dout) {
    extern __shared__ float sm[];
    uint32_t* smU = (uint32_t*)sm;
    const int tx = threadIdx.x;

    // ---- one-time staging ----
    for (int i = tx; i < 1024; i += TPB) smU[OW3 + i] = 0u;
    __syncthreads();
    for (int i = tx; i < HID * 64; i += TPB) {       // W2, K-permuted
        int o = i >> 6, kw = i & 63;
        int kc = 16 * (kw >> 3) + (kw & 7);
        smU[OW2 + o * 64 + (kw ^ ((o & 7) << 2))] =
            packh2(w2[o * HID + kc], w2[o * HID + kc + 8]);
    }
    for (int i = tx; i < HID * 24; i += TPB) {       // W1, natural K
        int o = i / 24, kw = i % 24;
        smU[OW1 + o * 32 + (kw ^ ((o & 7) << 2))] =
            packh2(w1[o * PERCC + 2 * kw], w1[o * PERCC + 2 * kw + 1]);
    }
    for (int i = tx; i < CIN * 64; i += TPB) {       // W3, K-permuted
        int o = i >> 6, kw = i & 63;
        int kc = 16 * (kw >> 3) + (kw & 7);
        smU[OW3 + o * 64 + (kw ^ ((o & 7) << 2))] =
            packh2(w3[o * HID + kc], w3[o * HID + kc + 8]);
    }
    for (int i = tx; i < 108; i += TPB) {            // conv weights packed
        int g = i / 9, q = i % 9;
        float4 v = make_float4(wp[(4 * g + 0) * 9 + q], wp[(4 * g + 1) * 9 + q],
                               wp[(4 * g + 2) * 9 + q], wp[(4 * g + 3) * 9 + q]);
        *(float4*)(sm + OWPK + i * 4) = v;
    }
    if (tx < 12)
        *(float4*)(sm + OBPK + tx * 4) =
            make_float4(bp[4 * tx], bp[4 * tx + 1], bp[4 * tx + 2], bp[4 * tx + 3]);
    if (tx < HID) { sm[OB1 + tx] = b1[tx]; sm[OB2 + tx] = b2[tx]; }
    __syncthreads();

    const uint32_t sbase = smem_u32(sm);
    const int w    = tx >> 5, lane = tx & 31;
    const int grp  = lane >> 2, t4 = lane & 3;
    const int quad = w >> 2;             // 0..3, owns px [64*quad, 64*quad+64)
    const int bid  = quad + 1;           // named barrier id
    const int cb   = (w & 3) * 32;       // channel base (32 ch per warp)
    const int pxb  = quad * 64;          // pixel base
    const int pxb3 = w * 16;             // L3 pixel base (within quad range)

    // ---- ldmatrix per-lane invariant addressing ----
    const int swlo = (lane & 1) << 2;
    const int swhi = (lane & 6) << 2;
    const int cA   = ((lane >> 4) << 2) ^ swlo;
    const int cB   = (((lane >> 3) & 1) << 2) ^ swlo;
    const int lr   = lane & 15;
    const int bRow = (lane & 7) + ((lane >> 4) << 3);

    uint32_t aW1[2], aW2[2], bP0[4], bH1[4];
#pragma unroll
    for (int i = 0; i < 2; i++) {
        aW1[i] = sbase + 4 * (OW1 + (cb + 16 * i + lr) * 32 + cA);
        aW2[i] = sbase + 4 * (OW2 + (cb + 16 * i + lr) * 64 + cA);
    }
#pragma unroll
    for (int j = 0; j < 4; j++) {
        bP0[j] = sbase + 4 * (OPH2 + (pxb + 16 * j + bRow) * 32 + cB);
        bH1[j] = sbase + 4 * (OH1 + (pxb + 16 * j + bRow) * 64 + cB);
    }
    const uint32_t aW3 = sbase + 4 * (OW3 + lr * 64 + cA);
    const uint32_t bH2 = sbase + 4 * (OH1 + (pxb3 + bRow) * 64 + cB);

    float b1v[2][2], b2v[2][2];
#pragma unroll
    for (int i = 0; i < 2; i++) {
        b1v[i][0] = sm[OB1 + cb + 16 * i + grp];
        b1v[i][1] = sm[OB1 + cb + 16 * i + 8 + grp];
        b2v[i][0] = sm[OB2 + cb + 16 * i + grp];
        b2v[i][1] = sm[OB2 + cb + 16 * i + 8 + grp];
    }

    // conv mapping: quad-local. 128 threads cover 64 px x 2 channel-halves.
    const int tq    = tx & 127;
    const int cpx   = pxb + (tq & 63);
    const int chalf = tq >> 6;

    // ---- prologue: conv for first tile (quad's rows) ----
    {
        int t0 = blockIdx.x;
        float win[6][9];
        conv_load(xin, hin, win, t0 >> 8, t0 & 255, cpx, chalf);
        conv_compute(win, sm, smU, cpx, chalf);
    }
    BARQ(bid);

    for (int tile = blockIdx.x; tile < NTILES; tile += gridDim.x) {
        const int b = tile >> 8;
        const int y = tile & 255;

        // ---- L1: 32ch x 64px per warp, K=48; relu-store -> h region ----
        {
            float acc[2][8][4];
#pragma unroll
            for (int i = 0; i < 2; i++)
#pragma unroll
                for (int j = 0; j < 8; j++) {
                    acc[i][j][0] = b1v[i][0];
                    acc[i][j][1] = b1v[i][0];
                    acc[i][j][2] = b1v[i][1];
                    acc[i][j][3] = b1v[i][1];
                }
#pragma unroll
            for (int s = 0; s < 3; s++) {
                uint32_t ds = (uint32_t)(((8 * s) ^ swhi) << 2);
                uint32_t a0[4], a1[4], bb[4][4];
                LDSM4(a0, aW1[0] + ds);
                LDSM4(a1, aW1[1] + ds);
#pragma unroll
                for (int jj = 0; jj < 4; jj++) LDSM4(bb[jj], bP0[jj] + ds);
#pragma unroll
                for (int jj = 0; jj < 4; jj++) {
                    mma16(acc[0][2 * jj],     a0, bb[jj][0], bb[jj][1]);
                    mma16(acc[1][2 * jj],     a1, bb[jj][0], bb[jj][1]);
                    mma16(acc[0][2 * jj + 1], a0, bb[jj][2], bb[jj][3]);
                    mma16(acc[1][2 * jj + 1], a1, bb[jj][2], bb[jj][3]);
                }
            }
#pragma unroll
            for (int i = 0; i < 2; i++) {
                int wi = (cb >> 1) + 8 * i + grp;
#pragma unroll
                for (int j = 0; j < 8; j++) {
                    float v0 = fmaxf(acc[i][j][0], 0.0f);
                    float v1 = fmaxf(acc[i][j][1], 0.0f);
                    float v2 = fmaxf(acc[i][j][2], 0.0f);
                    float v3 = fmaxf(acc[i][j][3], 0.0f);
                    int px0 = pxb + 8 * j + 2 * t4;
                    smU[OH1 + px0 * 64 + (wi ^ ((px0 & 7) << 2))] = packh2(v0, v2);
                    smU[OH1 + (px0 + 1) * 64 + (wi ^ (((px0 + 1) & 7) << 2))] =
                        packh2(v1, v3);
                }
            }
        }
        BARQ(bid);

        // ---- L2 MMA: 32ch x 64px per warp, K=128 ----
        float acc2[2][8][4];
        {
#pragma unroll
            for (int i = 0; i < 2; i++)
#pragma unroll
                for (int j = 0; j < 8; j++) {
                    acc2[i][j][0] = b2v[i][0];
                    acc2[i][j][1] = b2v[i][0];
                    acc2[i][j][2] = b2v[i][1];
                    acc2[i][j][3] = b2v[i][1];
                }
#pragma unroll
            for (int s = 0; s < 8; s++) {
                uint32_t ds = (uint32_t)(((8 * s) ^ swhi) << 2);
                uint32_t a0[4], a1[4], bb[4][4];
                LDSM4(a0, aW2[0] + ds);
                LDSM4(a1, aW2[1] + ds);
#pragma unroll
                for (int jj = 0; jj < 4; jj++) LDSM4(bb[jj], bH1[jj] + ds);
#pragma unroll
                for (int jj = 0; jj < 4; jj++) {
                    mma16(acc2[0][2 * jj],     a0, bb[jj][0], bb[jj][1]);
                    mma16(acc2[1][2 * jj],     a1, bb[jj][0], bb[jj][1]);
                    mma16(acc2[0][2 * jj + 1], a0, bb[jj][2], bb[jj][3]);
                    mma16(acc2[1][2 * jj + 1], a1, bb[jj][2], bb[jj][3]);
                }
            }
        }
        BARQ(bid);   // quad's h1 reads done before overwrite

        // ---- L2 store: relu -> h region (h2, overwrites h1 rows) ----
        {
#pragma unroll
            for (int i = 0; i < 2; i++) {
                int wi = (cb >> 1) + 8 * i + grp;
#pragma unroll
                for (int j = 0; j < 8; j++) {
                    float v0 = fmaxf(acc2[i][j][0], 0.0f);
                    float v1 = fmaxf(acc2[i][j][1], 0.0f);
                    float v2 = fmaxf(acc2[i][j][2], 0.0f);
                    float v3 = fmaxf(acc2[i][j][3], 0.0f);
                    int px0 = pxb + 8 * j + 2 * t4;
                    smU[OH1 + px0 * 64 + (wi ^ ((px0 & 7) << 2))] = packh2(v0, v2);
                    smU[OH1 + (px0 + 1) * 64 + (wi ^ (((px0 + 1) & 7) << 2))] =
                        packh2(v1, v3);
                }
            }
        }
        BARQ(bid);

        // ---- L3 phase: conv-LDG hoist, L3 MMA, epilogue, conv compute ----
        {
            int nt = tile + gridDim.x;
            bool havenext = nt < NTILES;
            float win[6][9];
            if (havenext)
                conv_load(xin, hin, win, nt >> 8, nt & 255, cpx, chalf);

            float acc[2][4];
#pragma unroll
            for (int j = 0; j < 2; j++)
#pragma unroll
                for (int q = 0; q < 4; q++) acc[j][q] = 0.0f;
#pragma unroll
            for (int s = 0; s < 8; s++) {
                uint32_t ds = (uint32_t)(((8 * s) ^ swhi) << 2);
                uint32_t a[4], bb[4];
                LDSM4(a, aW3 + ds);
                LDSM4(bb, bH2 + ds);
                mma16(acc[0], a, bb[0], bb[1]);
                mma16(acc[1], a, bb[2], bb[3]);
            }
            float* out_noise = dout + (size_t)BATCH * 9 * HW;
            float embv = (grp < CNOISE) ? __ldg(&g_emb[b * 3 + grp]) : 0.0f;
#pragma unroll
            for (int j = 0; j < 2; j++) {
                int px0 = pxb3 + 8 * j + 2 * t4;
                size_t yx = (size_t)y * WW + px0;
                if (grp < CNOISE) {
                    *(float2*)(out_noise + ((size_t)b * 3 + grp) * HW + yx) =
                        make_float2(acc[j][0] + embv, acc[j][1] + embv);
                } else {
                    *(float2*)(dout + ((size_t)b * 9 + (grp - 3)) * HW + yx) =
                        make_float2(acc[j][0], acc[j][1]);
                }
                if (grp < 4) {
                    *(float2*)(dout + ((size_t)b * 9 + (grp + 5)) * HW + yx) =
                        make_float2(acc[j][2], acc[j][3]);
                }
            }

            if (havenext)
                conv_compute(win, sm, smU, cpx, chalf);
        }
        BARQ(bid);
    }
}

extern "C" void kernel_launch(void* const* d_in, const int* in_sizes, int n_in,
                              void* d_out, int out_size) {
    const float* x      = (const float*)d_in[0];
    const float* hid    = (const float*)d_in[1];
    const int*   t      = (const int*)d_in[2];
    const float* wp     = (const float*)d_in[3];
    const float* bp     = (const float*)d_in[4];
    const float* w1     = (const float*)d_in[5];
    const float* b1     = (const float*)d_in[6];
    const float* w2     = (const float*)d_in[7];
    const float* b2     = (const float*)d_in[8];
    const float* w3     = (const float*)d_in[9];
    const float* w_time = (const float*)d_in[10];
    const float* b_time = (const float*)d_in[11];
    float* out = (float*)d_out;

    cudaFuncSetAttribute(canet_main,
                         cudaFuncAttributeMaxDynamicSharedMemorySize,
                         SMEM_BYTES);

    int nsm = 148;
    if (cudaDeviceGetAttribute(&nsm, cudaDevAttrMultiProcessorCount, 0)
        != cudaSuccess || nsm <= 0)
        nsm = 148;

    emb_kernel<<<BATCH, TDIM>>>(t, w_time, b_time);
    canet_main<<<nsm, TPB, SMEM_BYTES>>>(
        x, hid, wp, bp, w1, b1, w2, b2, w3, out);
}

// round 16
// speedup vs baseline: 1.3348x; 1.2954x over previous
#include <cuda_runtime.h>
#include <cuda_fp16.h>
#include <cstdint>

#define HH 256
#define WW 256
#define BATCH 16
#define HW 65536
#define CIN 12
#define CNOISE 3
#define PERCC 48
#define HID 128
#define TDIM 256
#define TPB 512
#define TP 256
#define NTILES (BATCH * HW / TP)   // 4096 (tile = one image row)

// SMEM word (b32) offsets  (154 KB total -> L1D carveout ~73KB for conv LDGs)
#define OW2   0       // W2 [128 rows][64 words] swizzled, K-permuted fp16-pairs
#define OW1   8192    // W1 [128 rows][32 words] (24 real) swizzled
#define OW3   12288   // W3 [16 rows][64 words] swizzled, K-permuted (rows 12-15 zero)
#define OWPK  13312   // conv weights packed: [12 grp][9 q][4 floats]
#define OBPK  13744   // conv bias packed: [12 grp][4 floats]
#define OB1   13792   // b1 128 fp32
#define OB2   13920   // b2 128 fp32
#define OH1   14048   // h region [256 px][64 words]: h1 then h2 (quad-private rows)
#define OPH2  30432   // perc SINGLE buffer [256 px][32 words] (quad-private rows)
#define SMEM_WORDS 38624
#define SMEM_BYTES (SMEM_WORDS * 4)   // 154496

typedef unsigned long long ull;

#define FMA2(d, a, b) \
    asm("fma.rn.f32x2 %0, %1, %2, %0;" : "+l"(d) : "l"(a), "l"(b))
#define PACKF(out, lo, hi) \
    asm("mov.b64 %0, {%1, %2};" : "=l"(out) : "f"(lo), "f"(hi))
#define UNPACKF(lo, hi, in) \
    asm("mov.b64 {%0, %1}, %2;" : "=f"(lo), "=f"(hi) : "l"(in))

// Quad-scoped named barrier: 4 warps / 128 threads, ids 1..4
#define BARQ(id) \
    asm volatile("bar.sync %0, 128;" :: "r"(id) : "memory")

static __device__ __forceinline__ uint32_t packh2(float lo, float hi) {
    __half2 h = __floats2half2_rn(lo, hi);
    return *(uint32_t*)&h;
}

static __device__ __forceinline__ uint32_t smem_u32(const void* p) {
    uint32_t a;
    asm("{ .reg .u64 t; cvta.to.shared.u64 t, %1; cvt.u32.u64 %0, t; }"
        : "=r"(a) : "l"(p));
    return a;
}

static __device__ __forceinline__ void mma16(float d[4], const uint32_t a[4],
                                             uint32_t b0, uint32_t b1) {
    asm volatile(
        "mma.sync.aligned.m16n8k16.row.col.f32.f16.f16.f32 "
        "{%0,%1,%2,%3}, {%4,%5,%6,%7}, {%8,%9}, {%0,%1,%2,%3};"
        : "+f"(d[0]), "+f"(d[1]), "+f"(d[2]), "+f"(d[3])
        : "r"(a[0]), "r"(a[1]), "r"(a[2]), "r"(a[3]), "r"(b0), "r"(b1));
}

#define LDSM4(r, a) \
    asm volatile("ldmatrix.sync.aligned.m8n8.x4.shared.b16 {%0,%1,%2,%3}, [%4];" \
        : "=r"((r)[0]), "=r"((r)[1]), "=r"((r)[2]), "=r"((r)[3]) : "r"(a))

__device__ float g_emb[BATCH * CNOISE];

// ---------------------------------------------------------------------------
__global__ void emb_kernel(const int* __restrict__ t,
                           const float* __restrict__ w_time,
                           const float* __restrict__ b_time) {
    __shared__ float ss[TDIM];
    int b = blockIdx.x, k = threadIdx.x;
    float tb = (float)t[b];
    int f = (k < TDIM / 2) ? k : (k - TDIM / 2);
    const double LN1E4 = 9.210340371976184;
    float invf = (float)exp(-LN1E4 * ((double)(2 * f) / 256.0));
    float ang = tb * invf;
    float pe = (float)((k < TDIM / 2) ? sin((double)ang) : cos((double)ang));
    ss[k] = pe / (1.0f + (float)exp(-(double)pe));
    __syncthreads();
    if (k < CNOISE) {
        float acc = b_time[k];
        for (int q = 0; q < TDIM; q++)
            acc = fmaf(ss[q], w_time[k * TDIM + q], acc);
        g_emb[b * CNOISE + k] = acc;
    }
}

// ---------------------------------------------------------------------------
// Depthwise conv: quad-local pixel cpx, channel half chalf -> perc rows.
// Single buffer is phase-safe: conv runs in the L3 phase, AFTER L1 consumed
// the previous tile's perc, and a BARQ separates it from the next L1.
// Load/compute kept fused: win[] dies immediately (no spill pressure).
// ---------------------------------------------------------------------------
static __device__ __forceinline__ void conv_tile(
    const float* __restrict__ xin, const float* __restrict__ hin,
    const float* sm, uint32_t* smU, int b, int y,
    int cpx, int chalf) {
    float win[6][9];
#pragma unroll
    for (int gi = 0; gi < 6; gi++) {
        int g = chalf * 6 + gi;
        const float* src = (g < CNOISE)
            ? (xin + ((size_t)b * CNOISE + g) * HW)
            : (hin + ((size_t)b * (CIN - CNOISE) + (g - CNOISE)) * HW);
#pragma unroll
        for (int dy = -1; dy <= 1; dy++)
#pragma unroll
            for (int dx = -1; dx <= 1; dx++) {
                int yy = y + dy, xx = cpx + dx;
                float v = 0.0f;
                if (yy >= 0 && yy < HH && xx >= 0 && xx < WW)
                    v = __ldg(src + yy * WW + xx);
                win[gi][(dy + 1) * 3 + (dx + 1)] = v;
            }
    }
    int swz = (cpx & 7) << 2;
#pragma unroll
    for (int gi = 0; gi < 6; gi++) {
        int g = chalf * 6 + gi;
        ulonglong2 bb = *(const ulonglong2*)(sm + OBPK + g * 4);
        ull a01 = bb.x, a23 = bb.y;
#pragma unroll
        for (int q = 0; q < 9; q++) {
            ull wd;
            PACKF(wd, win[gi][q], win[gi][q]);
            ulonglong2 ww = *(const ulonglong2*)(sm + OWPK + (g * 9 + q) * 4);
            FMA2(a01, wd, ww.x);
            FMA2(a23, wd, ww.y);
        }
        float a0, a1, a2, a3;
        UNPACKF(a0, a1, a01);
        UNPACKF(a2, a3, a23);
        *(uint2*)(smU + OPH2 + cpx * 32 + ((2 * g) ^ swz)) =
            make_uint2(packh2(a0, a1), packh2(a2, a3));
    }
}

// ---------------------------------------------------------------------------
// Persistent pipeline, fp16 m16n8k16, 16 warps in 4 independent quads.
// Proven-best configuration: quad drift via named barriers, ldmatrix.x4 with
// tile-invariant addressing, K-permuted inter-layer packing (no shfl),
// bias-initialized accumulators, single perc buffer (big L1D carveout).
// ---------------------------------------------------------------------------
__global__ void __launch_bounds__(TPB, 1)
canet_main(const float* __restrict__ xin, const float* __restrict__ hin,
           const float* __restrict__ wp, const float* __restrict__ bp,
           const float* __restrict__ w1, const float* __restrict__ b1,
           const float* __restrict__ w2, const float* __restrict__ b2,
           const float* __restrict__ w3, float* __restrict__ dout) {
    extern __shared__ float sm[];
    uint32_t* smU = (uint32_t*)sm;
    const int tx = threadIdx.x;

    // ---- one-time staging ----
    for (int i = tx; i < 1024; i += TPB) smU[OW3 + i] = 0u;
    __syncthreads();
    for (int i = tx; i < HID * 64; i += TPB) {       // W2, K-permuted
        int o = i >> 6, kw = i & 63;
        int kc = 16 * (kw >> 3) + (kw & 7);
        smU[OW2 + o * 64 + (kw ^ ((o & 7) << 2))] =
            packh2(w2[o * HID + kc], w2[o * HID + kc + 8]);
    }
    for (int i = tx; i < HID * 24; i += TPB) {       // W1, natural K
        int o = i / 24, kw = i % 24;
        smU[OW1 + o * 32 + (kw ^ ((o & 7) << 2))] =
            packh2(w1[o * PERCC + 2 * kw], w1[o * PERCC + 2 * kw + 1]);
    }
    for (int i = tx; i < CIN * 64; i += TPB) {       // W3, K-permuted
        int o = i >> 6, kw = i & 63;
        int kc = 16 * (kw >> 3) + (kw & 7);
        smU[OW3 + o * 64 + (kw ^ ((o & 7) << 2))] =
            packh2(w3[o * HID + kc], w3[o * HID + kc + 8]);
    }
    for (int i = tx; i < 108; i += TPB) {            // conv weights packed
        int g = i / 9, q = i % 9;
        float4 v = make_float4(wp[(4 * g + 0) * 9 + q], wp[(4 * g + 1) * 9 + q],
                               wp[(4 * g + 2) * 9 + q], wp[(4 * g + 3) * 9 + q]);
        *(float4*)(sm + OWPK + i * 4) = v;
    }
    if (tx < 12)
        *(float4*)(sm + OBPK + tx * 4) =
            make_float4(bp[4 * tx], bp[4 * tx + 1], bp[4 * tx + 2], bp[4 * tx + 3]);
    if (tx < HID) { sm[OB1 + tx] = b1[tx]; sm[OB2 + tx] = b2[tx]; }
    __syncthreads();

    const uint32_t sbase = smem_u32(sm);
    const int w    = tx >> 5, lane = tx & 31;
    const int grp  = lane >> 2, t4 = lane & 3;
    const int quad = w >> 2;             // 0..3, owns px [64*quad, 64*quad+64)
    const int bid  = quad + 1;           // named barrier id
    const int cb   = (w & 3) * 32;       // channel base (32 ch per warp)
    const int pxb  = quad * 64;          // pixel base
    const int pxb3 = w * 16;             // L3 pixel base (within quad range)

    // ---- ldmatrix per-lane invariant addressing ----
    const int swlo = (lane & 1) << 2;
    const int swhi = (lane & 6) << 2;
    const int cA   = ((lane >> 4) << 2) ^ swlo;
    const int cB   = (((lane >> 3) & 1) << 2) ^ swlo;
    const int lr   = lane & 15;
    const int bRow = (lane & 7) + ((lane >> 4) << 3);

    uint32_t aW1[2], aW2[2], bP0[4], bH1[4];
#pragma unroll
    for (int i = 0; i < 2; i++) {
        aW1[i] = sbase + 4 * (OW1 + (cb + 16 * i + lr) * 32 + cA);
        aW2[i] = sbase + 4 * (OW2 + (cb + 16 * i + lr) * 64 + cA);
    }
#pragma unroll
    for (int j = 0; j < 4; j++) {
        bP0[j] = sbase + 4 * (OPH2 + (pxb + 16 * j + bRow) * 32 + cB);
        bH1[j] = sbase + 4 * (OH1 + (pxb + 16 * j + bRow) * 64 + cB);
    }
    const uint32_t aW3 = sbase + 4 * (OW3 + lr * 64 + cA);
    const uint32_t bH2 = sbase + 4 * (OH1 + (pxb3 + bRow) * 64 + cB);

    float b1v[2][2], b2v[2][2];
#pragma unroll
    for (int i = 0; i < 2; i++) {
        b1v[i][0] = sm[OB1 + cb + 16 * i + grp];
        b1v[i][1] = sm[OB1 + cb + 16 * i + 8 + grp];
        b2v[i][0] = sm[OB2 + cb + 16 * i + grp];
        b2v[i][1] = sm[OB2 + cb + 16 * i + 8 + grp];
    }

    // conv mapping: quad-local. 128 threads cover 64 px x 2 channel-halves.
    const int tq    = tx & 127;
    const int cpx   = pxb + (tq & 63);
    const int chalf = tq >> 6;

    // ---- prologue: conv for first tile (quad's rows) ----
    {
        int t0 = blockIdx.x;
        conv_tile(xin, hin, sm, smU, t0 >> 8, t0 & 255, cpx, chalf);
    }
    BARQ(bid);

    for (int tile = blockIdx.x; tile < NTILES; tile += gridDim.x) {
        const int b = tile >> 8;
        const int y = tile & 255;

        // ---- L1: 32ch x 64px per warp, K=48; relu-store -> h region ----
        {
            float acc[2][8][4];
#pragma unroll
            for (int i = 0; i < 2; i++)
#pragma unroll
                for (int j = 0; j < 8; j++) {
                    acc[i][j][0] = b1v[i][0];
                    acc[i][j][1] = b1v[i][0];
                    acc[i][j][2] = b1v[i][1];
                    acc[i][j][3] = b1v[i][1];
                }
#pragma unroll
            for (int s = 0; s < 3; s++) {
                uint32_t ds = (uint32_t)(((8 * s) ^ swhi) << 2);
                uint32_t a0[4], a1[4], bb[4][4];
                LDSM4(a0, aW1[0] + ds);
                LDSM4(a1, aW1[1] + ds);
#pragma unroll
                for (int jj = 0; jj < 4; jj++) LDSM4(bb[jj], bP0[jj] + ds);
#pragma unroll
                for (int jj = 0; jj < 4; jj++) {
                    mma16(acc[0][2 * jj],     a0, bb[jj][0], bb[jj][1]);
                    mma16(acc[1][2 * jj],     a1, bb[jj][0], bb[jj][1]);
                    mma16(acc[0][2 * jj + 1], a0, bb[jj][2], bb[jj][3]);
                    mma16(acc[1][2 * jj + 1], a1, bb[jj][2], bb[jj][3]);
                }
            }
#pragma unroll
            for (int i = 0; i < 2; i++) {
                int wi = (cb >> 1) + 8 * i + grp;
#pragma unroll
                for (int j = 0; j < 8; j++) {
                    float v0 = fmaxf(acc[i][j][0], 0.0f);
                    float v1 = fmaxf(acc[i][j][1], 0.0f);
                    float v2 = fmaxf(acc[i][j][2], 0.0f);
                    float v3 = fmaxf(acc[i][j][3], 0.0f);
                    int px0 = pxb + 8 * j + 2 * t4;
                    smU[OH1 + px0 * 64 + (wi ^ ((px0 & 7) << 2))] = packh2(v0, v2);
                    smU[OH1 + (px0 + 1) * 64 + (wi ^ (((px0 + 1) & 7) << 2))] =
                        packh2(v1, v3);
                }
            }
        }
        BARQ(bid);

        // ---- L2 MMA: 32ch x 64px per warp, K=128 ----
        float acc2[2][8][4];
        {
#pragma unroll
            for (int i = 0; i < 2; i++)
#pragma unroll
                for (int j = 0; j < 8; j++) {
                    acc2[i][j][0] = b2v[i][0];
                    acc2[i][j][1] = b2v[i][0];
                    acc2[i][j][2] = b2v[i][1];
                    acc2[i][j][3] = b2v[i][1];
                }
#pragma unroll
            for (int s = 0; s < 8; s++) {
                uint32_t ds = (uint32_t)(((8 * s) ^ swhi) << 2);
                uint32_t a0[4], a1[4], bb[4][4];
                LDSM4(a0, aW2[0] + ds);
                LDSM4(a1, aW2[1] + ds);
#pragma unroll
                for (int jj = 0; jj < 4; jj++) LDSM4(bb[jj], bH1[jj] + ds);
#pragma unroll
                for (int jj = 0; jj < 4; jj++) {
                    mma16(acc2[0][2 * jj],     a0, bb[jj][0], bb[jj][1]);
                    mma16(acc2[1][2 * jj],     a1, bb[jj][0], bb[jj][1]);
                    mma16(acc2[0][2 * jj + 1], a0, bb[jj][2], bb[jj][3]);
                    mma16(acc2[1][2 * jj + 1], a1, bb[jj][2], bb[jj][3]);
                }
            }
        }
        BARQ(bid);   // quad's h1 reads done before overwrite

        // ---- L2 store: relu -> h region (h2, overwrites h1 rows) ----
        {
#pragma unroll
            for (int i = 0; i < 2; i++) {
                int wi = (cb >> 1) + 8 * i + grp;
#pragma unroll
                for (int j = 0; j < 8; j++) {
                    float v0 = fmaxf(acc2[i][j][0], 0.0f);
                    float v1 = fmaxf(acc2[i][j][1], 0.0f);
                    float v2 = fmaxf(acc2[i][j][2], 0.0f);
                    float v3 = fmaxf(acc2[i][j][3], 0.0f);
                    int px0 = pxb + 8 * j + 2 * t4;
                    smU[OH1 + px0 * 64 + (wi ^ ((px0 & 7) << 2))] = packh2(v0, v2);
                    smU[OH1 + (px0 + 1) * 64 + (wi ^ (((px0 + 1) & 7) << 2))] =
                        packh2(v1, v3);
                }
            }
        }
        BARQ(bid);

        // ---- L3 + epilogue + conv(next tile, quad's rows) ----
        {
            float acc[2][4];
#pragma unroll
            for (int j = 0; j < 2; j++)
#pragma unroll
                for (int q = 0; q < 4; q++) acc[j][q] = 0.0f;
#pragma unroll
            for (int s = 0; s < 8; s++) {
                uint32_t ds = (uint32_t)(((8 * s) ^ swhi) << 2);
                uint32_t a[4], bb[4];
                LDSM4(a, aW3 + ds);
                LDSM4(bb, bH2 + ds);
                mma16(acc[0], a, bb[0], bb[1]);
                mma16(acc[1], a, bb[2], bb[3]);
            }
            float* out_noise = dout + (size_t)BATCH * 9 * HW;
            float embv = (grp < CNOISE) ? __ldg(&g_emb[b * 3 + grp]) : 0.0f;
#pragma unroll
            for (int j = 0; j < 2; j++) {
                int px0 = pxb3 + 8 * j + 2 * t4;
                size_t yx = (size_t)y * WW + px0;
                if (grp < CNOISE) {
                    *(float2*)(out_noise + ((size_t)b * 3 + grp) * HW + yx) =
                        make_float2(acc[j][0] + embv, acc[j][1] + embv);
                } else {
                    *(float2*)(dout + ((size_t)b * 9 + (grp - 3)) * HW + yx) =
                        make_float2(acc[j][0], acc[j][1]);
                }
                if (grp < 4) {
                    *(float2*)(dout + ((size_t)b * 9 + (grp + 5)) * HW + yx) =
                        make_float2(acc[j][2], acc[j][3]);
                }
            }

            int nt = tile + gridDim.x;
            if (nt < NTILES)
                conv_tile(xin, hin, sm, smU, nt >> 8, nt & 255, cpx, chalf);
        }
        BARQ(bid);
    }
}

extern "C" void kernel_launch(void* const* d_in, const int* in_sizes, int n_in,
                              void* d_out, int out_size) {
    const float* x      = (const float*)d_in[0];
    const float* hid    = (const float*)d_in[1];
    const int*   t      = (const int*)d_in[2];
    const float* wp     = (const float*)d_in[3];
    const float* bp     = (const float*)d_in[4];
    const float* w1     = (const float*)d_in[5];
    const float* b1     = (const float*)d_in[6];
    const float* w2     = (const float*)d_in[7];
    const float* b2     = (const float*)d_in[8];
    const float* w3     = (const float*)d_in[9];
    const float* w_time = (const float*)d_in[10];
    const float* b_time = (const float*)d_in[11];
    float* out = (float*)d_out;

    cudaFuncSetAttribute(canet_main,
                         cudaFuncAttributeMaxDynamicSharedMemorySize,
                         SMEM_BYTES);

    int nsm = 148;
    if (cudaDeviceGetAttribute(&nsm, cudaDevAttrMultiProcessorCount, 0)
        != cudaSuccess || nsm <= 0)
        nsm = 148;

    emb_kernel<<<BATCH, TDIM>>>(t, w_time, b_time);
    canet_main<<<nsm, TPB, SMEM_BYTES>>>(
        x, hid, wp, bp, w1, b1, w2, b2, w3, out);
}